// round 1
// baseline (speedup 1.0000x reference)
#include <cuda_runtime.h>
#include <math.h>
#include <stdint.h>

// Problem-scale bounds (B*L rows; this problem: 4*4096 = 16384)
#define MAX_ROWS 32768

// ---------------- device scratch (no allocations allowed) ----------------
__device__ float g_coarse_sum;   // sum of gt * log(cm + 1e-6)
__device__ float g_fine_sum;     // sum of per_norm over selected
__device__ int   g_fine_cnt;     // count of selected
__device__ int   g_valid_any;    // any valid gt row
__device__ int   g_jfirst[MAX_ROWS];  // first j with gt>0 per row, -1 if none

__global__ void mc_init_kernel() {
    g_coarse_sum = 0.0f;
    g_fine_sum   = 0.0f;
    g_fine_cnt   = 0;
    g_valid_any  = 0;
}

// ---------------- kernel 1: one block per row of [B*L, L] ----------------
// Streams gt (dense read), gathers cm only where gt != 0 (sparse),
// computes per-row first j with gt>0.
__global__ void __launch_bounds__(256) mc_row_kernel(
    const float* __restrict__ cm,
    const float* __restrict__ gt,
    int L)
{
    const int row = blockIdx.x;
    const long long base = (long long)row * (long long)L;
    const float*  gr = gt + base;
    const float*  cr = cm + base;
    const float4* g4 = (const float4*)gr;
    const int nv = L >> 2;

    float lsum = 0.0f;
    int   lmin = 0x7fffffff;

    for (int v = threadIdx.x; v < nv; v += 256) {
        float4 g = g4[v];
        // fast path: fully-zero vector contributes nothing
        if (g.x != 0.0f || g.y != 0.0f || g.z != 0.0f || g.w != 0.0f) {
            const int j = v << 2;
            if (g.x != 0.0f) lsum += g.x * __logf(cr[j + 0] + 1e-6f);
            if (g.y != 0.0f) lsum += g.y * __logf(cr[j + 1] + 1e-6f);
            if (g.z != 0.0f) lsum += g.z * __logf(cr[j + 2] + 1e-6f);
            if (g.w != 0.0f) lsum += g.w * __logf(cr[j + 3] + 1e-6f);
            if      (g.x > 0.0f) lmin = min(lmin, j + 0);
            else if (g.y > 0.0f) lmin = min(lmin, j + 1);
            else if (g.z > 0.0f) lmin = min(lmin, j + 2);
            else if (g.w > 0.0f) lmin = min(lmin, j + 3);
        }
    }
    // scalar tail (L not multiple of 4)
    for (int j = (nv << 2) + threadIdx.x; j < L; j += 256) {
        float g = gr[j];
        if (g != 0.0f) lsum += g * __logf(cr[j] + 1e-6f);
        if (g > 0.0f)  lmin = min(lmin, j);
    }

    // warp reduce
    #pragma unroll
    for (int o = 16; o > 0; o >>= 1) {
        lsum += __shfl_down_sync(0xffffffffu, lsum, o);
        lmin  = min(lmin, __shfl_down_sync(0xffffffffu, lmin, o));
    }
    __shared__ float ws[8];
    __shared__ int   wm[8];
    const int wid = threadIdx.x >> 5;
    const int lid = threadIdx.x & 31;
    if (lid == 0) { ws[wid] = lsum; wm[wid] = lmin; }
    __syncthreads();
    if (threadIdx.x < 8) {
        lsum = ws[threadIdx.x];
        lmin = wm[threadIdx.x];
        #pragma unroll
        for (int o = 4; o > 0; o >>= 1) {
            lsum += __shfl_down_sync(0xffu, lsum, o);
            lmin  = min(lmin, __shfl_down_sync(0xffu, lmin, o));
        }
        if (threadIdx.x == 0) {
            if (lsum != 0.0f) atomicAdd(&g_coarse_sum, lsum);
            const bool valid = (lmin < 0x7fffffff);
            g_jfirst[row] = valid ? lmin : -1;
            if (valid) g_valid_any = 1;  // racy writes of the same value: fine
        }
    }
}

// ---------------- kernel 2: one block per predicted point n ----------------
// Finds first valid gt row in batch b with exact (x,y) equality; applies the
// <10px gate and accumulates fine-loss partials.
__global__ void __launch_bounds__(128) mc_match_kernel(
    const float* __restrict__ samples0,
    const float* __restrict__ samples1,
    const float* __restrict__ mkpts0,
    const float* __restrict__ mkpts1,
    int B, int L)
{
    const int n = blockIdx.x;
    const float bf = mkpts0[3 * n + 0];
    const float x  = mkpts0[3 * n + 1];
    const float y  = mkpts0[3 * n + 2];

    long long best = 0x7fffffffffffffffLL;  // pack: (j << 32) | jfirst

    bool bad = !(bf == bf);                 // NaN guard
    int b = 0;
    if (!bad) {
        b = (int)bf;
        bad = ((float)b != bf) || (b < 0) || (b >= B);
    }
    if (!bad) {
        const int rbase = b * L;
        const float2* s = (const float2*)(samples0 + (long long)rbase * 2);
        for (int j = threadIdx.x; j < L; j += 128) {
            const int jf = g_jfirst[rbase + j];   // -1 => invalid row
            if (jf >= 0) {
                const float2 p = s[j];
                if (p.x == x && p.y == y) {
                    const long long cand = ((long long)j << 32) | (uint32_t)jf;
                    best = min(best, cand);
                }
            }
        }
    }

    // block min-reduce of packed candidate
    #pragma unroll
    for (int o = 16; o > 0; o >>= 1)
        best = min(best, __shfl_down_sync(0xffffffffu, best, o));
    __shared__ long long sm[4];
    const int wid = threadIdx.x >> 5;
    const int lid = threadIdx.x & 31;
    if (lid == 0) sm[wid] = best;
    __syncthreads();
    if (threadIdx.x == 0) {
        best = min(min(sm[0], sm[1]), min(sm[2], sm[3]));
        if (best != 0x7fffffffffffffffLL) {
            const int jf = (int)(uint32_t)(best & 0xffffffffu);
            const float2 q = ((const float2*)samples1)[(long long)b * L + jf];
            const float dx = q.x - mkpts1[2 * n + 0];
            const float dy = q.y - mkpts1[2 * n + 1];
            const float nrm = sqrtf(dx * dx + dy * dy);
            if (nrm < 10.0f) {
                atomicAdd(&g_fine_sum, nrm);
                atomicAdd(&g_fine_cnt, 1);
            }
        }
    }
}

// ---------------- kernel 3: finalize ----------------
__global__ void mc_finalize_kernel(float* __restrict__ out, float Bf) {
    const float coarse = -g_coarse_sum / Bf;
    float fine;
    if (g_valid_any) {
        fine = (g_fine_cnt > 0) ? (g_fine_sum / (float)g_fine_cnt) : 10.0f;
    } else {
        fine = 1e-6f;
    }
    out[0] = 1.0f * coarse + 1000.0f * fine;
    out[1] = coarse;
    out[2] = fine;
}

extern "C" void kernel_launch(void* const* d_in, const int* in_sizes, int n_in,
                              void* d_out, int out_size)
{
    const float* cm       = (const float*)d_in[0];  // [B,L,L]
    const float* gt       = (const float*)d_in[1];  // [B,L,L]
    const float* samples0 = (const float*)d_in[2];  // [B,L,2]
    const float* samples1 = (const float*)d_in[3];  // [B,L,2]
    const float* mkpts0   = (const float*)d_in[4];  // [N,3]
    const float* mkpts1   = (const float*)d_in[5];  // [N,2]
    float* out = (float*)d_out;

    const long long BL = (long long)in_sizes[2] / 2;       // B*L
    const int L = (int)((long long)in_sizes[0] / BL);      // B*L*L / (B*L)
    const int B = (int)(BL / L);
    const int N = in_sizes[4] / 3;
    const int rows = B * L;

    mc_init_kernel<<<1, 1>>>();
    mc_row_kernel<<<rows, 256>>>(cm, gt, L);
    mc_match_kernel<<<N, 128>>>(samples0, samples1, mkpts0, mkpts1, B, L);
    mc_finalize_kernel<<<1, 1>>>(out, (float)B);
}

// round 2
// speedup vs baseline: 1.2316x; 1.2316x over previous
#include <cuda_runtime.h>
#include <math.h>
#include <stdint.h>

// Problem-scale bounds (B*L rows; this problem: 4*4096 = 16384)
#define MAX_ROWS    32768
#define MAX_MBLOCKS 2048
#define PPB         32     // points per match block

// ---------------- device scratch (no allocations allowed) ----------------
// All arrays are fully overwritten every launch -> no init kernel needed.
__device__ float g_rowsum[MAX_ROWS];   // per-row sum of gt*log(cm+1e-6)
__device__ int   g_jfirst[MAX_ROWS];   // first j with gt>0 per row, -1 if none
__device__ float g_msum[MAX_MBLOCKS];  // per-match-block fine sum
__device__ int   g_mcnt[MAX_MBLOCKS];  // per-match-block fine count

// ---------------- kernel 1: one block (128 thr) per row of [B*L, L] -------
// Streams gt with front-batched float4 loads (MLP=8/thread); gathers cm only
// where gt != 0; records first j with gt>0.
__global__ void __launch_bounds__(128) mc_row_kernel(
    const float* __restrict__ cm,
    const float* __restrict__ gt,
    int L)
{
    const int row = blockIdx.x;
    const long long base = (long long)row * (long long)L;
    const float*  gr = gt + base;
    const float*  cr = cm + base;
    const float4* g4 = (const float4*)gr;
    const int nv = L >> 2;

    float lsum = 0.0f;
    int   lmin = 0x7fffffff;

    // fast path: chunks of 1024 float4s (4096 floats), 8 loads/thread batched
    int v0 = 0;
    for (; v0 + 1024 <= nv; v0 += 1024) {
        float4 r[8];
        #pragma unroll
        for (int i = 0; i < 8; i++)
            r[i] = g4[v0 + threadIdx.x + i * 128];
        #pragma unroll
        for (int i = 0; i < 8; i++) {
            const float4 g = r[i];
            if (g.x != 0.0f || g.y != 0.0f || g.z != 0.0f || g.w != 0.0f) {
                const int j = (v0 + threadIdx.x + i * 128) << 2;
                if (g.x != 0.0f) lsum += g.x * __logf(cr[j + 0] + 1e-6f);
                if (g.y != 0.0f) lsum += g.y * __logf(cr[j + 1] + 1e-6f);
                if (g.z != 0.0f) lsum += g.z * __logf(cr[j + 2] + 1e-6f);
                if (g.w != 0.0f) lsum += g.w * __logf(cr[j + 3] + 1e-6f);
                if      (g.x > 0.0f) lmin = min(lmin, j + 0);
                else if (g.y > 0.0f) lmin = min(lmin, j + 1);
                else if (g.z > 0.0f) lmin = min(lmin, j + 2);
                else if (g.w > 0.0f) lmin = min(lmin, j + 3);
            }
        }
    }
    // remainder float4s
    for (int v = v0 + threadIdx.x; v < nv; v += 128) {
        const float4 g = g4[v];
        if (g.x != 0.0f || g.y != 0.0f || g.z != 0.0f || g.w != 0.0f) {
            const int j = v << 2;
            if (g.x != 0.0f) lsum += g.x * __logf(cr[j + 0] + 1e-6f);
            if (g.y != 0.0f) lsum += g.y * __logf(cr[j + 1] + 1e-6f);
            if (g.z != 0.0f) lsum += g.z * __logf(cr[j + 2] + 1e-6f);
            if (g.w != 0.0f) lsum += g.w * __logf(cr[j + 3] + 1e-6f);
            if      (g.x > 0.0f) lmin = min(lmin, j + 0);
            else if (g.y > 0.0f) lmin = min(lmin, j + 1);
            else if (g.z > 0.0f) lmin = min(lmin, j + 2);
            else if (g.w > 0.0f) lmin = min(lmin, j + 3);
        }
    }
    // scalar tail
    for (int j = (nv << 2) + threadIdx.x; j < L; j += 128) {
        const float g = gr[j];
        if (g != 0.0f) lsum += g * __logf(cr[j] + 1e-6f);
        if (g > 0.0f)  lmin = min(lmin, j);
    }

    // block reduce (4 warps)
    #pragma unroll
    for (int o = 16; o > 0; o >>= 1) {
        lsum += __shfl_down_sync(0xffffffffu, lsum, o);
        lmin  = min(lmin, __shfl_down_sync(0xffffffffu, lmin, o));
    }
    __shared__ float ws[4];
    __shared__ int   wm[4];
    const int wid = threadIdx.x >> 5;
    if ((threadIdx.x & 31) == 0) { ws[wid] = lsum; wm[wid] = lmin; }
    __syncthreads();
    if (threadIdx.x == 0) {
        lsum = ws[0] + ws[1] + ws[2] + ws[3];
        lmin = min(min(wm[0], wm[1]), min(wm[2], wm[3]));
        g_rowsum[row] = lsum;
        g_jfirst[row] = (lmin < 0x7fffffff) ? lmin : -1;
    }
}

// ---------------- kernel 2: 32 points per block, scan all B*L rows --------
// Register-resident x-prefilter; smem atomicMin for first-match; per-block
// partial fine sums written to slots (no global atomics, no init).
__global__ void __launch_bounds__(512) mc_match_kernel(
    const float* __restrict__ samples0,
    const float* __restrict__ samples1,
    const float* __restrict__ mkpts0,
    const float* __restrict__ mkpts1,
    int B, int L, int N)
{
    __shared__ float sX[PPB], sY[PPB], sB[PPB];
    __shared__ unsigned long long sBest[PPB];
    const int tid = threadIdx.x;

    if (tid < PPB) {
        const int n = blockIdx.x * PPB + tid;
        if (n < N) {
            sB[tid] = mkpts0[3 * n + 0];
            sX[tid] = mkpts0[3 * n + 1];
            sY[tid] = mkpts0[3 * n + 2];
        } else {
            const float nanv = __int_as_float(0x7fc00000);  // NaN: never equal
            sB[tid] = nanv; sX[tid] = nanv; sY[tid] = nanv;
        }
        sBest[tid] = 0xffffffffffffffffULL;
    }
    __syncthreads();

    float X[PPB];
    #pragma unroll
    for (int i = 0; i < PPB; i++) X[i] = sX[i];

    const int BL = B * L;
    const float2* s = (const float2*)samples0;

    for (int r = tid; r < BL; r += 512) {
        const float2 p = s[r];
        bool any = false;
        #pragma unroll
        for (int i = 0; i < PPB; i++) any |= (p.x == X[i]);
        if (any) {
            const int jf = g_jfirst[r];
            if (jf >= 0) {
                const float bf = (float)(r / L);
                const unsigned long long cand =
                    ((unsigned long long)(unsigned)r << 32) | (unsigned)jf;
                #pragma unroll
                for (int i = 0; i < PPB; i++) {
                    if (p.x == X[i] && p.y == sY[i] && bf == sB[i])
                        atomicMin(&sBest[i], cand);
                }
            }
        }
    }
    __syncthreads();

    if (tid < PPB) {
        float fs = 0.0f;
        int   fc = 0;
        const int n = blockIdx.x * PPB + tid;
        const unsigned long long best = sBest[tid];
        if (n < N && best != 0xffffffffffffffffULL) {
            const int r  = (int)(best >> 32);
            const int jf = (int)(unsigned)(best & 0xffffffffu);
            const int b  = r / L;
            const float2 q = ((const float2*)samples1)[(long long)b * L + jf];
            const float dx = q.x - mkpts1[2 * n + 0];
            const float dy = q.y - mkpts1[2 * n + 1];
            const float nrm = sqrtf(dx * dx + dy * dy);
            if (nrm < 10.0f) { fs = nrm; fc = 1; }
        }
        #pragma unroll
        for (int o = 16; o > 0; o >>= 1) {
            fs += __shfl_down_sync(0xffffffffu, fs, o);
            fc += __shfl_down_sync(0xffffffffu, fc, o);
        }
        if (tid == 0) { g_msum[blockIdx.x] = fs; g_mcnt[blockIdx.x] = fc; }
    }
}

// ---------------- kernel 3: finalize (one 256-thread block) ----------------
__global__ void __launch_bounds__(256) mc_finalize_kernel(
    float* __restrict__ out, int rows, int mblocks, float Bf)
{
    const int tid = threadIdx.x;
    float cs = 0.0f;
    int   vany = 0;
    for (int i = tid; i < rows; i += 256) {
        cs += g_rowsum[i];
        vany |= (g_jfirst[i] >= 0);
    }
    float fs = 0.0f;
    int   fc = 0;
    for (int i = tid; i < mblocks; i += 256) {
        fs += g_msum[i];
        fc += g_mcnt[i];
    }

    #pragma unroll
    for (int o = 16; o > 0; o >>= 1) {
        cs += __shfl_down_sync(0xffffffffu, cs, o);
        fs += __shfl_down_sync(0xffffffffu, fs, o);
        fc += __shfl_down_sync(0xffffffffu, fc, o);
        vany |= __shfl_down_sync(0xffffffffu, vany, o);
    }
    __shared__ float wcs[8], wfs[8];
    __shared__ int   wfc[8], wva[8];
    const int wid = tid >> 5;
    if ((tid & 31) == 0) { wcs[wid] = cs; wfs[wid] = fs; wfc[wid] = fc; wva[wid] = vany; }
    __syncthreads();
    if (tid == 0) {
        cs = 0.0f; fs = 0.0f; fc = 0; vany = 0;
        #pragma unroll
        for (int i = 0; i < 8; i++) { cs += wcs[i]; fs += wfs[i]; fc += wfc[i]; vany |= wva[i]; }
        const float coarse = -cs / Bf;
        float fine;
        if (vany) fine = (fc > 0) ? (fs / (float)fc) : 10.0f;
        else      fine = 1e-6f;
        out[0] = coarse + 1000.0f * fine;
        out[1] = coarse;
        out[2] = fine;
    }
}

extern "C" void kernel_launch(void* const* d_in, const int* in_sizes, int n_in,
                              void* d_out, int out_size)
{
    const float* cm       = (const float*)d_in[0];  // [B,L,L]
    const float* gt       = (const float*)d_in[1];  // [B,L,L]
    const float* samples0 = (const float*)d_in[2];  // [B,L,2]
    const float* samples1 = (const float*)d_in[3];  // [B,L,2]
    const float* mkpts0   = (const float*)d_in[4];  // [N,3]
    const float* mkpts1   = (const float*)d_in[5];  // [N,2]
    float* out = (float*)d_out;

    const long long BL = (long long)in_sizes[2] / 2;       // B*L
    const int L = (int)((long long)in_sizes[0] / BL);      // B*L*L / (B*L)
    const int B = (int)(BL / L);
    const int N = in_sizes[4] / 3;
    const int rows = B * L;
    const int mblocks = (N + PPB - 1) / PPB;

    mc_row_kernel<<<rows, 128>>>(cm, gt, L);
    mc_match_kernel<<<mblocks, 512>>>(samples0, samples1, mkpts0, mkpts1, B, L, N);
    mc_finalize_kernel<<<1, 256>>>(out, rows, mblocks, (float)B);
}

// round 3
// speedup vs baseline: 1.7318x; 1.4061x over previous
#include <cuda_runtime.h>
#include <math.h>
#include <stdint.h>

#define MAX_ROWS    32768
#define HSZ         32768                 // hash table slots (power of 2)
#define MAX_BBLK    (MAX_ROWS / 256)      // build-kernel blocks (128)
#define MAX_PBLK    64                    // probe-kernel blocks

// ---------------- device scratch (no allocations allowed) ----------------
// Everything is fully overwritten each launch in dependency order:
//   row kernel:   g_rowsum, g_jfirst, resets g_head
//   build kernel: g_next, g_head (inserts), g_csum, g_vany
//   probe kernel: g_msum, g_mcnt
__device__ float g_rowsum[MAX_ROWS];
__device__ int   g_jfirst[MAX_ROWS];
__device__ int   g_head[HSZ];
__device__ int   g_next[MAX_ROWS];
__device__ float g_csum[MAX_BBLK];
__device__ int   g_vany[MAX_BBLK];
__device__ float g_msum[MAX_PBLK];
__device__ int   g_mcnt[MAX_PBLK];

__device__ __forceinline__ uint32_t hash_x(float x) {
    uint32_t u = __float_as_uint(x) * 2654435761u;
    return (u >> 17) & (HSZ - 1);         // top 15 bits
}

// ---------------- kernel 1: one block (128 thr) per row of [B*L, L] -------
// Streams gt (read-once -> __ldcs), gathers cm only where gt != 0,
// records first j with gt>0. Also resets the hash heads for kernel 2.
__global__ void __launch_bounds__(128) mc_row_kernel(
    const float* __restrict__ cm,
    const float* __restrict__ gt,
    int L)
{
    // interleaved hash-head reset (covered by the first HSZ/128 blocks)
    for (int i = blockIdx.x * 128 + threadIdx.x; i < HSZ; i += gridDim.x * 128)
        g_head[i] = -1;

    const int row = blockIdx.x;
    const long long base = (long long)row * (long long)L;
    const float*  gr = gt + base;
    const float*  cr = cm + base;
    const float4* g4 = (const float4*)gr;
    const int nv = L >> 2;

    float lsum = 0.0f;
    int   lmin = 0x7fffffff;

    // chunks of 1024 float4s: 8 streaming loads/thread, front-batched (MLP=8)
    int v0 = 0;
    for (; v0 + 1024 <= nv; v0 += 1024) {
        float4 r[8];
        #pragma unroll
        for (int i = 0; i < 8; i++)
            r[i] = __ldcs(&g4[v0 + threadIdx.x + i * 128]);
        #pragma unroll
        for (int i = 0; i < 8; i++) {
            const float4 g = r[i];
            if (g.x != 0.0f || g.y != 0.0f || g.z != 0.0f || g.w != 0.0f) {
                const int j = (v0 + threadIdx.x + i * 128) << 2;
                if (g.x != 0.0f) lsum += g.x * __logf(cr[j + 0] + 1e-6f);
                if (g.y != 0.0f) lsum += g.y * __logf(cr[j + 1] + 1e-6f);
                if (g.z != 0.0f) lsum += g.z * __logf(cr[j + 2] + 1e-6f);
                if (g.w != 0.0f) lsum += g.w * __logf(cr[j + 3] + 1e-6f);
                if      (g.x > 0.0f) lmin = min(lmin, j + 0);
                else if (g.y > 0.0f) lmin = min(lmin, j + 1);
                else if (g.z > 0.0f) lmin = min(lmin, j + 2);
                else if (g.w > 0.0f) lmin = min(lmin, j + 3);
            }
        }
    }
    // remainder float4s
    for (int v = v0 + threadIdx.x; v < nv; v += 128) {
        const float4 g = __ldcs(&g4[v]);
        if (g.x != 0.0f || g.y != 0.0f || g.z != 0.0f || g.w != 0.0f) {
            const int j = v << 2;
            if (g.x != 0.0f) lsum += g.x * __logf(cr[j + 0] + 1e-6f);
            if (g.y != 0.0f) lsum += g.y * __logf(cr[j + 1] + 1e-6f);
            if (g.z != 0.0f) lsum += g.z * __logf(cr[j + 2] + 1e-6f);
            if (g.w != 0.0f) lsum += g.w * __logf(cr[j + 3] + 1e-6f);
            if      (g.x > 0.0f) lmin = min(lmin, j + 0);
            else if (g.y > 0.0f) lmin = min(lmin, j + 1);
            else if (g.z > 0.0f) lmin = min(lmin, j + 2);
            else if (g.w > 0.0f) lmin = min(lmin, j + 3);
        }
    }
    // scalar tail
    for (int j = (nv << 2) + threadIdx.x; j < L; j += 128) {
        const float g = gr[j];
        if (g != 0.0f) lsum += g * __logf(cr[j] + 1e-6f);
        if (g > 0.0f)  lmin = min(lmin, j);
    }

    // block reduce (4 warps)
    #pragma unroll
    for (int o = 16; o > 0; o >>= 1) {
        lsum += __shfl_down_sync(0xffffffffu, lsum, o);
        lmin  = min(lmin, __shfl_down_sync(0xffffffffu, lmin, o));
    }
    __shared__ float ws[4];
    __shared__ int   wm[4];
    const int wid = threadIdx.x >> 5;
    if ((threadIdx.x & 31) == 0) { ws[wid] = lsum; wm[wid] = lmin; }
    __syncthreads();
    if (threadIdx.x == 0) {
        lsum = ws[0] + ws[1] + ws[2] + ws[3];
        lmin = min(min(wm[0], wm[1]), min(wm[2], wm[3]));
        g_rowsum[row] = lsum;
        g_jfirst[row] = (lmin < 0x7fffffff) ? lmin : -1;
    }
}

// ---------------- kernel 2: hash build + coarse partial reduce -------------
// One thread per row: insert valid rows into x-keyed hash chains; block
// also reduces its 256 rowsums -> g_csum[block], vany -> g_vany[block].
__global__ void __launch_bounds__(256) mc_build_kernel(
    const float* __restrict__ samples0, int rows)
{
    const int tid = threadIdx.x;
    const int r = blockIdx.x * 256 + tid;

    float cs = 0.0f;
    int   va = 0;
    if (r < rows) {
        cs = g_rowsum[r];
        const int jf = g_jfirst[r];
        va = (jf >= 0);
        if (va) {
            const float x = ((const float2*)samples0)[r].x;
            g_next[r] = atomicExch(&g_head[hash_x(x)], r);
        }
    }

    #pragma unroll
    for (int o = 16; o > 0; o >>= 1) {
        cs += __shfl_down_sync(0xffffffffu, cs, o);
        va |= __shfl_down_sync(0xffffffffu, va, o);
    }
    __shared__ float wcs[8];
    __shared__ int   wva[8];
    const int wid = tid >> 5;
    if ((tid & 31) == 0) { wcs[wid] = cs; wva[wid] = va; }
    __syncthreads();
    if (tid == 0) {
        cs = 0.0f; va = 0;
        #pragma unroll
        for (int i = 0; i < 8; i++) { cs += wcs[i]; va |= wva[i]; }
        g_csum[blockIdx.x] = cs;
        g_vany[blockIdx.x] = va;
    }
}

// ---------------- kernel 3: probe (one thread per predicted point) --------
__global__ void __launch_bounds__(256) mc_probe_kernel(
    const float* __restrict__ samples0,
    const float* __restrict__ samples1,
    const float* __restrict__ mkpts0,
    const float* __restrict__ mkpts1,
    int L, int N)
{
    const int tid = threadIdx.x;
    const int n = blockIdx.x * 256 + tid;

    float fs = 0.0f;
    int   fc = 0;
    if (n < N) {
        const float bf = mkpts0[3 * n + 0];
        const float x  = mkpts0[3 * n + 1];
        const float y  = mkpts0[3 * n + 2];
        const float2* s0 = (const float2*)samples0;

        int best = 0x7fffffff;
        for (int r = g_head[hash_x(x)]; r >= 0; r = g_next[r]) {
            const float2 p = s0[r];
            if (p.x == x && p.y == y && (float)(r / L) == bf)
                best = min(best, r);
        }
        if (best != 0x7fffffff) {
            const int jf = g_jfirst[best];
            const int b  = best / L;
            const float2 q = ((const float2*)samples1)[(long long)b * L + jf];
            const float dx = q.x - mkpts1[2 * n + 0];
            const float dy = q.y - mkpts1[2 * n + 1];
            const float nrm = sqrtf(dx * dx + dy * dy);
            if (nrm < 10.0f) { fs = nrm; fc = 1; }
        }
    }

    #pragma unroll
    for (int o = 16; o > 0; o >>= 1) {
        fs += __shfl_down_sync(0xffffffffu, fs, o);
        fc += __shfl_down_sync(0xffffffffu, fc, o);
    }
    __shared__ float wfs[8];
    __shared__ int   wfc[8];
    const int wid = tid >> 5;
    if ((tid & 31) == 0) { wfs[wid] = fs; wfc[wid] = fc; }
    __syncthreads();
    if (tid == 0) {
        fs = 0.0f; fc = 0;
        #pragma unroll
        for (int i = 0; i < 8; i++) { fs += wfs[i]; fc += wfc[i]; }
        g_msum[blockIdx.x] = fs;
        g_mcnt[blockIdx.x] = fc;
    }
}

// ---------------- kernel 4: finalize (one warp-heavy small block) ----------
__global__ void __launch_bounds__(128) mc_finalize_kernel(
    float* __restrict__ out, int nb, int pb, float Bf)
{
    const int tid = threadIdx.x;
    float cs = 0.0f, fs = 0.0f;
    int   va = 0,    fc = 0;
    for (int i = tid; i < nb; i += 128) { cs += g_csum[i]; va |= g_vany[i]; }
    for (int i = tid; i < pb; i += 128) { fs += g_msum[i]; fc += g_mcnt[i]; }

    #pragma unroll
    for (int o = 16; o > 0; o >>= 1) {
        cs += __shfl_down_sync(0xffffffffu, cs, o);
        fs += __shfl_down_sync(0xffffffffu, fs, o);
        fc += __shfl_down_sync(0xffffffffu, fc, o);
        va |= __shfl_down_sync(0xffffffffu, va, o);
    }
    __shared__ float wcs[4], wfs[4];
    __shared__ int   wfc[4], wva[4];
    const int wid = tid >> 5;
    if ((tid & 31) == 0) { wcs[wid] = cs; wfs[wid] = fs; wfc[wid] = fc; wva[wid] = va; }
    __syncthreads();
    if (tid == 0) {
        cs = wcs[0] + wcs[1] + wcs[2] + wcs[3];
        fs = wfs[0] + wfs[1] + wfs[2] + wfs[3];
        fc = wfc[0] + wfc[1] + wfc[2] + wfc[3];
        va = wva[0] | wva[1] | wva[2] | wva[3];
        const float coarse = -cs / Bf;
        float fine;
        if (va) fine = (fc > 0) ? (fs / (float)fc) : 10.0f;
        else    fine = 1e-6f;
        out[0] = coarse + 1000.0f * fine;
        out[1] = coarse;
        out[2] = fine;
    }
}

extern "C" void kernel_launch(void* const* d_in, const int* in_sizes, int n_in,
                              void* d_out, int out_size)
{
    const float* cm       = (const float*)d_in[0];  // [B,L,L]
    const float* gt       = (const float*)d_in[1];  // [B,L,L]
    const float* samples0 = (const float*)d_in[2];  // [B,L,2]
    const float* samples1 = (const float*)d_in[3];  // [B,L,2]
    const float* mkpts0   = (const float*)d_in[4];  // [N,3]
    const float* mkpts1   = (const float*)d_in[5];  // [N,2]
    float* out = (float*)d_out;

    const long long BL = (long long)in_sizes[2] / 2;       // B*L
    const int L = (int)((long long)in_sizes[0] / BL);      // B*L*L / (B*L)
    const int B = (int)(BL / L);
    const int N = in_sizes[4] / 3;
    const int rows = B * L;
    const int nb = (rows + 255) / 256;   // build blocks
    const int pb = (N + 255) / 256;      // probe blocks

    mc_row_kernel<<<rows, 128>>>(cm, gt, L);
    mc_build_kernel<<<nb, 256>>>(samples0, rows);
    mc_probe_kernel<<<pb, 256>>>(samples0, samples1, mkpts0, mkpts1, L, N);
    mc_finalize_kernel<<<1, 128>>>(out, nb, pb, (float)B);
}